// round 16
// baseline (speedup 1.0000x reference)
#include <cuda_runtime.h>
#include <cuda_bf16.h>

#define Bn 1024
#define Tn 512
#define Cn 53
#define BOSi 1
#define EOSi 2
#define NCH 64

__device__ float g_chunk[Bn*NCH];
__device__ float g_score[Bn];
__device__ unsigned g_ticket;

__device__ __forceinline__ unsigned cvt2(float lo, float hi){
    unsigned r; asm("cvt.rn.bf16x2.f32 %0, %1, %2;" : "=r"(r) : "f"(hi), "f"(lo)); return r;
}
__device__ __forceinline__ void mma_acc(float* d, const unsigned* a, unsigned b0, unsigned b1){
    asm("mma.sync.aligned.m16n8k16.row.col.f32.bf16.bf16.f32 "
        "{%0,%1,%2,%3},{%4,%5,%6,%7},{%8,%9},{%0,%1,%2,%3};"
        : "+f"(d[0]),"+f"(d[1]),"+f"(d[2]),"+f"(d[3])
        : "r"(a[0]),"r"(a[1]),"r"(a[2]),"r"(a[3]),"r"(b0),"r"(b1));
}

__global__ void __launch_bounds__(128, 3)
crf_mma_kernel(const float* __restrict__ em, const int* __restrict__ tags,
               const float* __restrict__ mask, const float* __restrict__ trans,
               float* __restrict__ out)
{
    __shared__ float trs[Cn*Cn];
    __shared__ uint2 EF[4][7][32];   // bf16 B-fragments of E=exp(T), 64x56
    __shared__ float eos_sm[64];
    __shared__ float rr[4];
    __shared__ int slast;

    const int tid = threadIdx.x, lane = tid&31, w = tid>>5;
    const int q = lane&3, g = lane>>2;

    for (int i=tid;i<Cn*Cn;i+=128) trs[i]=trans[i];
    __syncthreads();
    if (tid<64) eos_sm[tid] = (tid<Cn)? __expf(trs[tid*Cn+EOSi]) : 0.f;
    if (tid<32){
        for (int kt=0;kt<4;kt++) for (int nt=0;nt<7;nt++){
            int n = 8*nt + (tid>>2);
            int k0 = 16*kt + 2*(tid&3);
            float e00=0,e01=0,e10=0,e11=0;
            if (n<Cn){
                if (k0  <Cn) e00=__expf(trs[(k0  )*Cn+n]);
                if (k0+1<Cn) e01=__expf(trs[(k0+1)*Cn+n]);
                if (k0+8<Cn) e10=__expf(trs[(k0+8)*Cn+n]);
                if (k0+9<Cn) e11=__expf(trs[(k0+9)*Cn+n]);
            }
            EF[kt][nt][tid] = make_uint2(cvt2(e00,e01), cvt2(e10,e11));
        }
    }
    __syncthreads();

    // warp -> half a batch: 32 of 64 chunks. chunk = 32*half + row,
    // row = g + 8*(idx&1) + 16*(idx>>1).
    const int gw   = blockIdx.x*4 + w;
    const int b    = gw>>1;
    const int half = gw&1;
    const float* emb = em + (size_t)b*Tn*Cn;
    const int* tg = tags + b*Tn;

    float ms=0;
    for (int i=lane;i<Tn;i+=32) ms += mask[b*Tn+i];
    for (int o=16;o;o>>=1) ms += __shfl_xor_sync(~0u,ms,o);
    const int tl=(int)ms;
    const int len = tl-2;

    int bs[4], iS[4], iE[4];
    float L[4]={0,0,0,0}, contrib[4]={0,0,0,0}, sc[4]={1,1,1,1};
    int imax=0;
    #pragma unroll
    for (int idx=0;idx<4;idx++){
        int ch = 32*half + g + 8*(idx&1) + 16*(idx>>1);
        int s = 2 + (len*ch)/NCH;
        int e = 2 + (len*(ch+1))/NCH;
        bs[idx] = (ch==0)? 2 : s-8;          // BURN=8
        iS[idx] = (ch==0)? -1 : 7;
        iE[idx] = e-1-bs[idx];
        if (iE[idx]+1>imax) imax=iE[idx]+1;
    }
    for (int o=16;o;o>>=1){ int v=__shfl_xor_sync(~0u,imax,o); if(v>imax) imax=v; }

    // init P: chunk0 (half==0, ch==0 rows) = exact alpha_1, others uniform 1
    float P[2][7][4];
    #pragma unroll
    for (int mt=0;mt<2;mt++)
    #pragma unroll
    for (int nt=0;nt<7;nt++)
    #pragma unroll
    for (int r=0;r<4;r++){
        int h=r>>1, d=r&1;
        int j = 8*nt + 2*q + d;
        int ch = 32*half + g + 8*h + 16*mt;
        float v;
        if (j>=Cn) v=0.f;
        else if (ch==0) v=__expf(trs[BOSi*Cn+j] + __ldg(emb+Cn+j));
        else v=1.f;
        P[mt][nt][r]=v;
    }

    for (int i0=0;i0<imax;i0+=4){
      #pragma unroll
      for (int ii=0;ii<4;ii++){
        const int i = i0+ii;
        float ev[4][14];
        #pragma unroll
        for (int idx=0;idx<4;idx++){
            int t = bs[idx]+i; if (t>510) t=510;
            const float* rp = emb + (size_t)t*Cn;
            #pragma unroll
            for (int nt=0;nt<7;nt++){
                int c0 = 8*nt+2*q; int c1 = c0+1;
                if (c0>52) c0=52; if (c1>52) c1=52;
                ev[idx][2*nt]  =__ldg(rp+c0);
                ev[idx][2*nt+1]=__ldg(rp+c1);
            }
        }
        // P = (sc .* P) @ E  (C-frag chains into A-frag; k-tile 3 upper half = 0)
        #pragma unroll
        for (int mt=0;mt<2;mt++){
            unsigned Af[4][4];
            #pragma unroll
            for (int kt=0;kt<3;kt++){
                Af[kt][0]=cvt2(sc[2*mt]*P[mt][2*kt][0],    sc[2*mt]*P[mt][2*kt][1]);
                Af[kt][1]=cvt2(sc[2*mt+1]*P[mt][2*kt][2],  sc[2*mt+1]*P[mt][2*kt][3]);
                Af[kt][2]=cvt2(sc[2*mt]*P[mt][2*kt+1][0],  sc[2*mt]*P[mt][2*kt+1][1]);
                Af[kt][3]=cvt2(sc[2*mt+1]*P[mt][2*kt+1][2],sc[2*mt+1]*P[mt][2*kt+1][3]);
            }
            Af[3][0]=cvt2(sc[2*mt]*P[mt][6][0],   sc[2*mt]*P[mt][6][1]);
            Af[3][1]=cvt2(sc[2*mt+1]*P[mt][6][2], sc[2*mt+1]*P[mt][6][3]);
            Af[3][2]=0u; Af[3][3]=0u;
            #pragma unroll
            for (int nt=0;nt<7;nt++){
                P[mt][nt][0]=0.f;P[mt][nt][1]=0.f;P[mt][nt][2]=0.f;P[mt][nt][3]=0.f;
                #pragma unroll
                for (int kt=0;kt<4;kt++){
                    uint2 bb = EF[kt][nt][lane];
                    mma_acc(P[mt][nt], Af[kt], bb.x, bb.y);
                }
            }
        }
        // emission exp + multiply
        #pragma unroll
        for (int idx=0;idx<4;idx++)
        #pragma unroll
        for (int k=0;k<14;k++) ev[idx][k]=__expf(ev[idx][k]);
        #pragma unroll
        for (int mt=0;mt<2;mt++)
        #pragma unroll
        for (int nt=0;nt<7;nt++){
            P[mt][nt][0]*=ev[2*mt][2*nt];   P[mt][nt][1]*=ev[2*mt][2*nt+1];
            P[mt][nt][2]*=ev[2*mt+1][2*nt]; P[mt][nt][3]*=ev[2*mt+1][2*nt+1];
        }
        // per-chain row sums (quad reduction)
        float rs[4];
        #pragma unroll
        for (int idx=0;idx<4;idx++){
            int mt=idx>>1, h=idx&1;
            float s=0;
            #pragma unroll
            for (int nt=0;nt<7;nt++) s += P[mt][nt][2*h]+P[mt][nt][2*h+1];
            s += __shfl_xor_sync(~0u,s,1); s += __shfl_xor_sync(~0u,s,2);
            rs[idx]=s;
        }
        // bookkeeping; EOS dot only for chunk 63's quad at its end step
        #pragma unroll
        for (int idx=0;idx<4;idx++){
            float lrs = __logf(rs[idx]);
            float lev = lrs;
            if (idx==3){
                if (half==1 && g==7 && i==iE[3]){
                    unsigned m = __activemask();
                    float s=0;
                    #pragma unroll
                    for (int nt=0;nt<7;nt++)
                        s += P[1][nt][2]*eos_sm[8*nt+2*q] + P[1][nt][3]*eos_sm[8*nt+2*q+1];
                    s += __shfl_xor_sync(m,s,1); s += __shfl_xor_sync(m,s,2);
                    lev = __logf(s);
                }
            }
            if (i==iS[idx]) contrib[idx] -= L[idx]+lrs;
            if (i==iE[idx]) contrib[idx] += L[idx]+lev;
            if (ii==3){ L[idx]+=lrs; sc[idx]=__fdividef(1.f,rs[idx]); }
            else sc[idx]=1.f;
        }
      }
    }

    // gold-path score: half-0 warp of each batch
    if (half==0){
        float scv=0;
        for (int t=2+lane; t<tl; t+=32){
            int a=tg[t-1], c=tg[t];
            scv += emb[(size_t)t*Cn+c] + trs[a*Cn+c];
        }
        for (int o=16;o;o>>=1) scv += __shfl_xor_sync(~0u,scv,o);
        if (lane==0){
            int t1=tg[1];
            float first = trs[BOSi*Cn+t1] + emb[Cn+t1];
            int lt=tg[tl];
            g_score[b] = first + scv + trs[lt*Cn+EOSi];
        }
    }
    if (q==0){
        #pragma unroll
        for (int idx=0;idx<4;idx++){
            int ch = 32*half + g + 8*(idx&1) + 16*(idx>>1);
            g_chunk[b*NCH+ch] = contrib[idx];
        }
    }

    // fused last-block reduction
    __threadfence();
    __syncthreads();
    if (tid==0) slast = (atomicAdd(&g_ticket,1u)==(unsigned)(gridDim.x-1)) ? 1 : 0;
    __syncthreads();
    if (slast){
        __threadfence();
        float acc=0;
        for (int i=tid;i<Bn*NCH;i+=128) acc += __ldcg(&g_chunk[i]);
        for (int i=tid;i<Bn;i+=128)     acc -= __ldcg(&g_score[i]);
        for (int o=16;o;o>>=1) acc += __shfl_xor_sync(~0u,acc,o);
        if (lane==0) rr[w]=acc;
        __syncthreads();
        if (tid==0){ out[0]=rr[0]+rr[1]+rr[2]+rr[3]; g_ticket=0; }
    }
}

extern "C" void kernel_launch(void* const* d_in, const int* in_sizes, int n_in,
                              void* d_out, int out_size)
{
    const float* em    = (const float*)d_in[0];
    const int*   tags  = (const int*)  d_in[1];
    const float* mask  = (const float*)d_in[2];
    const float* trans = (const float*)d_in[3];
    float* out = (float*)d_out;

    crf_mma_kernel<<<Bn/2, 128>>>(em, tags, mask, trans, out);
}

// round 17
// speedup vs baseline: 1.3878x; 1.3878x over previous
#include <cuda_runtime.h>
#include <cuda_bf16.h>

#define Bn 1024
#define Tn 512
#define Cn 53
#define BOSi 1
#define EOSi 2
#define NCH 32
#define MAXOFS (510*212)

__device__ float g_chunk[Bn*NCH];
__device__ float g_score[Bn];
__device__ unsigned g_ticket;

__device__ __forceinline__ unsigned cvt2(float lo, float hi){
    unsigned r; asm("cvt.rn.bf16x2.f32 %0, %1, %2;" : "=r"(r) : "f"(hi), "f"(lo)); return r;
}
__device__ __forceinline__ void mma_acc(float* d, const unsigned* a, unsigned b0, unsigned b1){
    asm("mma.sync.aligned.m16n8k16.row.col.f32.bf16.bf16.f32 "
        "{%0,%1,%2,%3},{%4,%5,%6,%7},{%8,%9},{%0,%1,%2,%3};"
        : "+f"(d[0]),"+f"(d[1]),"+f"(d[2]),"+f"(d[3])
        : "r"(a[0]),"r"(a[1]),"r"(a[2]),"r"(a[3]),"r"(b0),"r"(b1));
}
#define CPA16(dst, src) \
    asm volatile("cp.async.cg.shared.global [%0], [%1], 16;" :: "r"(dst), "l"(src))

__global__ void __launch_bounds__(128, 3)
crf_mma_kernel(const float* __restrict__ em, const int* __restrict__ tags,
               const float* __restrict__ mask, const float* __restrict__ trans,
               float* __restrict__ out)
{
    __shared__ uint2 EF[4][7][32];      // bf16 B-fragments of E=exp(T), 64x56
    __shared__ float eos_sm[64];
    __shared__ float evs[4][32][68];    // staged emission rows (aligned windows)
    __shared__ int   ptrTab[4][32];     // per-warp row byte-offsets (bs*212)
    __shared__ float rr[4];
    __shared__ int slast;

    const int tid = threadIdx.x, lane = tid&31, w = tid>>5;
    const int q = lane&3, g = lane>>2;

    // zero evs once (pads + first-step stale safety)
    for (int z=tid; z<4*32*68; z+=128) ((float*)evs)[z]=0.f;
    if (tid<64) eos_sm[tid] = (tid<Cn)? __expf(__ldg(trans + tid*Cn + EOSi)) : 0.f;
    if (tid<32){
        for (int kt=0;kt<4;kt++) for (int nt=0;nt<7;nt++){
            int n = 8*nt + (tid>>2);
            int k0 = 16*kt + 2*(tid&3);
            float e00=0,e01=0,e10=0,e11=0;
            if (n<Cn){
                if (k0  <Cn) e00=__expf(__ldg(trans + (k0  )*Cn + n));
                if (k0+1<Cn) e01=__expf(__ldg(trans + (k0+1)*Cn + n));
                if (k0+8<Cn) e10=__expf(__ldg(trans + (k0+8)*Cn + n));
                if (k0+9<Cn) e11=__expf(__ldg(trans + (k0+9)*Cn + n));
            }
            EF[kt][nt][tid] = make_uint2(cvt2(e00,e01), cvt2(e10,e11));
        }
    }
    __syncthreads();

    // warp -> ONE batch, 32 chunks. row = g + 8*(idx&1) + 16*(idx>>1) = chunk id.
    const int b = blockIdx.x*4 + w;
    const float* emb = em + (size_t)b*Tn*Cn;
    const char*  embB = (const char*)emb;
    const int* tg = tags + b*Tn;

    float ms=0;
    for (int i=lane;i<Tn;i+=32) ms += mask[b*Tn+i];
    for (int o=16;o;o>>=1) ms += __shfl_xor_sync(~0u,ms,o);
    const int tl=(int)ms;
    const int len = tl-2;

    int bs[4], iS[4], iE[4];
    float L[4]={0,0,0,0}, contrib[4]={0,0,0,0}, sc[4]={1,1,1,1};
    int imax=0;
    #pragma unroll
    for (int idx=0;idx<4;idx++){
        int ch = g + 8*(idx&1) + 16*(idx>>1);
        int s = 2 + (len*ch)/NCH;
        int e = 2 + (len*(ch+1))/NCH;
        bs[idx] = (ch==0)? 2 : s-8;          // BURN=8
        iS[idx] = (ch==0)? -1 : 7;
        iE[idx] = e-1-bs[idx];
        if (iE[idx]+1>imax) imax=iE[idx]+1;
    }
    for (int o=16;o;o>>=1){ int v=__shfl_xor_sync(~0u,imax,o); if(v>imax) imax=v; }

    if (q==0){
        #pragma unroll
        for (int idx=0;idx<4;idx++)
            ptrTab[w][g + 8*(idx&1) + 16*(idx>>1)] = bs[idx]*212;
    }
    __syncwarp();

    // init P: chunk0 = exact alpha_1 (prob domain), others uniform 1
    float P[2][7][4];
    #pragma unroll
    for (int mt=0;mt<2;mt++)
    #pragma unroll
    for (int nt=0;nt<7;nt++)
    #pragma unroll
    for (int r=0;r<4;r++){
        int h=r>>1, d=r&1;
        int j = 8*nt + 2*q + d;
        int ch = g + 8*h + 16*mt;
        float v;
        if (j>=Cn) v=0.f;
        else if (ch==0) v=__expf(__ldg(trans + BOSi*Cn + j) + __ldg(emb+Cn+j));
        else v=1.f;
        P[mt][nt][r]=v;
    }

    const unsigned evb = (unsigned)__cvta_generic_to_shared(&evs[w][0][0]);

    for (int i0=0;i0<imax;i0+=4){
      #pragma unroll
      for (int ii=0;ii<4;ii++){
        const int i = i0+ii;
        const int i212 = i*212;

        // ---- coalesced async stage of the 32 emission rows for this step ----
        #pragma unroll
        for (int j=0;j<16;j++){
            int R = 2*j + (lane>>4);
            int c16 = (lane&15)*16;
            int o = ptrTab[w][R] + i212;
            o = o < MAXOFS ? o : MAXOFS;
            int oa = o & ~15;
            if ((lane&15) < 14)
                CPA16(evb + (unsigned)(R*272 + c16), embB + oa + c16);
        }
        asm volatile("cp.async.commit_group;" ::: "memory");

        // ---- P = (sc .* P) @ E  (C-frag chains into A-frag; kt3 upper = 0) ----
        #pragma unroll
        for (int mt=0;mt<2;mt++){
            unsigned Af[4][4];
            #pragma unroll
            for (int kt=0;kt<3;kt++){
                Af[kt][0]=cvt2(sc[2*mt]*P[mt][2*kt][0],    sc[2*mt]*P[mt][2*kt][1]);
                Af[kt][1]=cvt2(sc[2*mt+1]*P[mt][2*kt][2],  sc[2*mt+1]*P[mt][2*kt][3]);
                Af[kt][2]=cvt2(sc[2*mt]*P[mt][2*kt+1][0],  sc[2*mt]*P[mt][2*kt+1][1]);
                Af[kt][3]=cvt2(sc[2*mt+1]*P[mt][2*kt+1][2],sc[2*mt+1]*P[mt][2*kt+1][3]);
            }
            Af[3][0]=cvt2(sc[2*mt]*P[mt][6][0],   sc[2*mt]*P[mt][6][1]);
            Af[3][1]=cvt2(sc[2*mt+1]*P[mt][6][2], sc[2*mt+1]*P[mt][6][3]);
            Af[3][2]=0u; Af[3][3]=0u;
            #pragma unroll
            for (int nt=0;nt<7;nt++){
                P[mt][nt][0]=0.f;P[mt][nt][1]=0.f;P[mt][nt][2]=0.f;P[mt][nt][3]=0.f;
                #pragma unroll
                for (int kt=0;kt<4;kt++){
                    uint2 bb = EF[kt][nt][lane];
                    mma_acc(P[mt][nt], Af[kt], bb.x, bb.y);
                }
            }
        }

        asm volatile("cp.async.wait_group 0;" ::: "memory");
        __syncwarp();

        // ---- emission exp-multiply from staged smem (shift = t&3) ----
        int sh[4];
        #pragma unroll
        for (int idx=0;idx<4;idx++){ int t=bs[idx]+i; if(t>510)t=510; sh[idx]=t&3; }
        #pragma unroll
        for (int mt=0;mt<2;mt++){
            const float* e0 = &evs[w][g+16*mt]  [sh[2*mt]   + 2*q];
            const float* e1 = &evs[w][g+8+16*mt][sh[2*mt+1] + 2*q];
            #pragma unroll
            for (int nt=0;nt<7;nt++){
                P[mt][nt][0]*=__expf(e0[8*nt]);   P[mt][nt][1]*=__expf(e0[8*nt+1]);
                P[mt][nt][2]*=__expf(e1[8*nt]);   P[mt][nt][3]*=__expf(e1[8*nt+1]);
            }
        }

        // ---- per-chain row sums (quad reduction) ----
        float rs[4];
        #pragma unroll
        for (int idx=0;idx<4;idx++){
            int mt=idx>>1, h=idx&1;
            float s=0;
            #pragma unroll
            for (int nt=0;nt<7;nt++) s += P[mt][nt][2*h]+P[mt][nt][2*h+1];
            s += __shfl_xor_sync(~0u,s,1); s += __shfl_xor_sync(~0u,s,2);
            rs[idx]=s;
        }
        // bookkeeping; EOS dot only for chunk 31's quad at its end step
        #pragma unroll
        for (int idx=0;idx<4;idx++){
            float lrs = __logf(rs[idx]);
            float lev = lrs;
            if (idx==3){
                if (g==7 && i==iE[3]){
                    unsigned m = __activemask();
                    float s=0;
                    #pragma unroll
                    for (int nt=0;nt<7;nt++)
                        s += P[1][nt][2]*eos_sm[8*nt+2*q] + P[1][nt][3]*eos_sm[8*nt+2*q+1];
                    s += __shfl_xor_sync(m,s,1); s += __shfl_xor_sync(m,s,2);
                    lev = __logf(s);
                }
            }
            if (i==iS[idx]) contrib[idx] -= L[idx]+lrs;
            if (i==iE[idx]) contrib[idx] += L[idx]+lev;
            if (ii==3){ L[idx]+=lrs; sc[idx]=__fdividef(1.f,rs[idx]); }
            else sc[idx]=1.f;
        }
      }
    }

    // gold-path score: whole warp on this batch
    {
        float scv=0;
        for (int t=2+lane; t<tl; t+=32){
            int a=tg[t-1], c=tg[t];
            scv += emb[(size_t)t*Cn+c] + __ldg(trans + a*Cn + c);
        }
        for (int o=16;o;o>>=1) scv += __shfl_xor_sync(~0u,scv,o);
        if (lane==0){
            int t1=tg[1];
            float first = __ldg(trans + BOSi*Cn + t1) + emb[Cn+t1];
            int lt=tg[tl];
            g_score[b] = first + scv + __ldg(trans + lt*Cn + EOSi);
        }
    }
    if (q==0){
        #pragma unroll
        for (int idx=0;idx<4;idx++){
            int ch = g + 8*(idx&1) + 16*(idx>>1);
            g_chunk[b*NCH+ch] = contrib[idx];
        }
    }

    // fused last-block reduction
    __threadfence();
    __syncthreads();
    if (tid==0) slast = (atomicAdd(&g_ticket,1u)==(unsigned)(gridDim.x-1)) ? 1 : 0;
    __syncthreads();
    if (slast){
        __threadfence();
        float acc=0;
        for (int i=tid;i<Bn*NCH;i+=128) acc += __ldcg(&g_chunk[i]);
        for (int i=tid;i<Bn;i+=128)     acc -= __ldcg(&g_score[i]);
        for (int o=16;o;o>>=1) acc += __shfl_xor_sync(~0u,acc,o);
        if (lane==0) rr[w]=acc;
        __syncthreads();
        if (tid==0){ out[0]=rr[0]+rr[1]+rr[2]+rr[3]; g_ticket=0; }
    }
}

extern "C" void kernel_launch(void* const* d_in, const int* in_sizes, int n_in,
                              void* d_out, int out_size)
{
    const float* em    = (const float*)d_in[0];
    const int*   tags  = (const int*)  d_in[1];
    const float* mask  = (const float*)d_in[2];
    const float* trans = (const float*)d_in[3];
    float* out = (float*)d_out;

    crf_mma_kernel<<<Bn/4, 128>>>(em, tags, mask, trans, out);
}